// round 2
// baseline (speedup 1.0000x reference)
#include <cuda_runtime.h>
#include <cuda_bf16.h>

// Problem constants
#define BT_    64000          // B*T
#define FIN_   1024
#define GV_    640            // GROUPS*NUM_VARS
#define NV_    320
#define VD_    128            // VAR_DIM
#define QELEMS (BT_ * 256)    // q output elements

// Scratch (no cudaMalloc allowed): logits buffer + reduction accumulators
__device__ float        g_logits[BT_ * GV_];
__device__ float        g_probsum[GV_];
__device__ unsigned int g_counts[GV_];

// ---------------------------------------------------------------------------
// Kernel 0: zero the global accumulators (graph replays must be deterministic)
// ---------------------------------------------------------------------------
__global__ void zero_kernel() {
    int i = blockIdx.x * blockDim.x + threadIdx.x;
    if (i < GV_) {
        g_probsum[i] = 0.0f;
        g_counts[i]  = 0u;
    }
}

// ---------------------------------------------------------------------------
// Kernel 1: fp32 tiled GEMM  logits[M,N] = X[M,K] @ W[N,K]^T + bias
// BM=128, BN=64, BK=16; 256 threads; 8x4 outputs per thread.
// Both operands are K-contiguous (row-major [*,1024]) -> float4 global loads.
// ---------------------------------------------------------------------------
__global__ __launch_bounds__(256) void gemm_kernel(const float* __restrict__ X,
                                                   const float* __restrict__ W,
                                                   const float* __restrict__ bias) {
    __shared__ float As[16][132];  // [k][m], padded stride 132 (16B-aligned, conflict-free)
    __shared__ float Bs[16][68];   // [k][n], padded stride 68

    const int tid = threadIdx.x;
    const int tx  = tid & 15;      // n sub-tile (0..15) -> 4 cols
    const int ty  = tid >> 4;      // m sub-tile (0..15) -> 8 rows
    const int m0  = blockIdx.y * 128;
    const int n0  = blockIdx.x * 64;

    const int rA = tid >> 2;          // 0..63
    const int c4 = (tid & 3) << 2;    // 0,4,8,12

    const float* xA0 = X + (size_t)(m0 + rA) * FIN_ + c4;
    const float* xA1 = xA0 + (size_t)64 * FIN_;
    const float* wB  = W + (size_t)(n0 + rA) * FIN_ + c4;

    float acc[8][4];
#pragma unroll
    for (int i = 0; i < 8; i++)
#pragma unroll
        for (int j = 0; j < 4; j++) acc[i][j] = 0.0f;

    for (int k0 = 0; k0 < FIN_; k0 += 16) {
        const float4 a0 = *(const float4*)(xA0 + k0);
        const float4 a1 = *(const float4*)(xA1 + k0);
        const float4 b0 = *(const float4*)(wB + k0);

        __syncthreads();
        As[c4 + 0][rA] = a0.x;  As[c4 + 1][rA] = a0.y;
        As[c4 + 2][rA] = a0.z;  As[c4 + 3][rA] = a0.w;
        As[c4 + 0][rA + 64] = a1.x;  As[c4 + 1][rA + 64] = a1.y;
        As[c4 + 2][rA + 64] = a1.z;  As[c4 + 3][rA + 64] = a1.w;
        Bs[c4 + 0][rA] = b0.x;  Bs[c4 + 1][rA] = b0.y;
        Bs[c4 + 2][rA] = b0.z;  Bs[c4 + 3][rA] = b0.w;
        __syncthreads();

#pragma unroll
        for (int kk = 0; kk < 16; kk++) {
            const float4 av0 = *(const float4*)&As[kk][ty * 8];
            const float4 av1 = *(const float4*)&As[kk][ty * 8 + 4];
            const float4 bv  = *(const float4*)&Bs[kk][tx * 4];
            const float a[8] = {av0.x, av0.y, av0.z, av0.w, av1.x, av1.y, av1.z, av1.w};
            const float b[4] = {bv.x, bv.y, bv.z, bv.w};
#pragma unroll
            for (int i = 0; i < 8; i++)
#pragma unroll
                for (int j = 0; j < 4; j++) acc[i][j] = fmaf(a[i], b[j], acc[i][j]);
        }
    }

    const float4 bb = *(const float4*)(bias + n0 + tx * 4);
#pragma unroll
    for (int i = 0; i < 8; i++) {
        const int row = m0 + ty * 8 + i;
        float4 o;
        o.x = acc[i][0] + bb.x;
        o.y = acc[i][1] + bb.y;
        o.z = acc[i][2] + bb.z;
        o.w = acc[i][3] + bb.w;
        *(float4*)&g_logits[(size_t)row * GV_ + n0 + tx * 4] = o;
    }
}

// ---------------------------------------------------------------------------
// Kernel 2: epilogue. 1 warp per (row, group); 8 warps/CTA; 64 rows/CTA.
//  - raw argmax -> shared count histogram
//  - softmax probs accumulated in per-warp registers -> shared -> global atomics
//  - argmax(logits + gumbel) -> gather codebook row into q
// ---------------------------------------------------------------------------
__global__ __launch_bounds__(256) void epi_kernel(const float* __restrict__ GMB,
                                                  const float* __restrict__ CB,
                                                  float* __restrict__ out) {
    __shared__ float        sprob[GV_];
    __shared__ unsigned int scnt[GV_];
    const int tid = threadIdx.x;
    for (int i = tid; i < GV_; i += 256) { sprob[i] = 0.0f; scnt[i] = 0u; }
    __syncthreads();

    const int warp = tid >> 5;
    const int lane = tid & 31;
    const int g    = warp & 1;           // group
    const int slot = warp >> 1;          // 0..3
    const int rbase = blockIdx.x * 64 + slot;

    float pacc[10];
#pragma unroll
    for (int j = 0; j < 10; j++) pacc[j] = 0.0f;

    for (int it = 0; it < 16; it++) {
        const int row = rbase + it * 4;
        const float* lp = g_logits + (size_t)row * GV_ + g * NV_;

        float lv[10];
#pragma unroll
        for (int j = 0; j < 10; j++) lv[j] = lp[j * 32 + lane];

        // ---- raw argmax (first-occurrence tie rule: strict >, min index) ----
        float bm = lv[0];
        int   bi = lane;
#pragma unroll
        for (int j = 1; j < 10; j++) {
            if (lv[j] > bm) { bm = lv[j]; bi = j * 32 + lane; }
        }
#pragma unroll
        for (int off = 16; off > 0; off >>= 1) {
            const float om = __shfl_xor_sync(0xffffffffu, bm, off);
            const int   oi = __shfl_xor_sync(0xffffffffu, bi, off);
            if (om > bm || (om == bm && oi < bi)) { bm = om; bi = oi; }
        }
        if (lane == 0) atomicAdd(&scnt[g * NV_ + bi], 1u);

        // ---- softmax accumulate ----
        float ev[10];
        float s = 0.0f;
#pragma unroll
        for (int j = 0; j < 10; j++) { ev[j] = __expf(lv[j] - bm); s += ev[j]; }
#pragma unroll
        for (int off = 16; off > 0; off >>= 1) s += __shfl_xor_sync(0xffffffffu, s, off);
        const float inv = 1.0f / s;
#pragma unroll
        for (int j = 0; j < 10; j++) pacc[j] += ev[j] * inv;

        // ---- gumbel argmax -> q gather ----
        const float* gp = GMB + (size_t)row * GV_ + g * NV_;
        float bm2 = lv[0] + gp[lane];
        int   bi2 = lane;
#pragma unroll
        for (int j = 1; j < 10; j++) {
            const float t = lv[j] + gp[j * 32 + lane];
            if (t > bm2) { bm2 = t; bi2 = j * 32 + lane; }
        }
#pragma unroll
        for (int off = 16; off > 0; off >>= 1) {
            const float om = __shfl_xor_sync(0xffffffffu, bm2, off);
            const int   oi = __shfl_xor_sync(0xffffffffu, bi2, off);
            if (om > bm2 || (om == bm2 && oi < bi2)) { bm2 = om; bi2 = oi; }
        }

        const float4* src = (const float4*)(CB + (size_t)(g * NV_ + bi2) * VD_);
        float4*       dst = (float4*)(out + (size_t)(row * 2 + g) * VD_);
        dst[lane] = src[lane];  // 32 lanes x 16B = 512B = full codebook row
    }

    // merge per-warp prob accumulators: shared (4 warps/group collide) then global
#pragma unroll
    for (int j = 0; j < 10; j++) atomicAdd(&sprob[g * NV_ + j * 32 + lane], pacc[j]);
    __syncthreads();
    for (int i = tid; i < GV_; i += 256) {
        atomicAdd(&g_probsum[i], sprob[i]);
        atomicAdd(&g_counts[i], scnt[i]);
    }
}

// ---------------------------------------------------------------------------
// Kernel 3: perplexity scalars. out layout: [q (16,384,000) | code_ppl | prob_ppl]
// One warp; each lane walks 10 codes per group with stride 32, shuffle-reduce.
// ---------------------------------------------------------------------------
__global__ void fin_kernel(float* __restrict__ out) {
    const int lane = threadIdx.x;  // 32 threads
    const float invBT = 1.0f / (float)BT_;

    float Hs[2], Hc[2];
#pragma unroll
    for (int g = 0; g < 2; g++) {
        float hs = 0.0f, hc = 0.0f;
        for (int j = 0; j < 10; j++) {
            const int v = g * NV_ + j * 32 + lane;
            const float p = g_probsum[v] * invBT;
            const float c = (float)g_counts[v] * invBT;
            hs += p * logf(p + 1e-7f);
            hc += c * logf(c + 1e-7f);
        }
#pragma unroll
        for (int off = 16; off > 0; off >>= 1) {
            hs += __shfl_xor_sync(0xffffffffu, hs, off);
            hc += __shfl_xor_sync(0xffffffffu, hc, off);
        }
        Hs[g] = hs; Hc[g] = hc;
    }
    if (lane == 0) {
        out[QELEMS]     = expf(-Hc[0]) + expf(-Hc[1]);  // code_perplexity
        out[QELEMS + 1] = expf(-Hs[0]) + expf(-Hs[1]);  // prob_perplexity
    }
}

// ---------------------------------------------------------------------------
// Launch
// inputs: 0=x [32,2000,1024] f32, 1=proj_w [640,1024] f32, 2=proj_b [640] f32,
//         3=codebook [640,128] f32, 4=gumbel [64000,640] f32
// output: f32, 16,384,002 elements (q flattened, then 2 scalars)
// ---------------------------------------------------------------------------
extern "C" void kernel_launch(void* const* d_in, const int* in_sizes, int n_in,
                              void* d_out, int out_size) {
    (void)in_sizes; (void)n_in; (void)out_size;
    const float* X    = (const float*)d_in[0];
    const float* W    = (const float*)d_in[1];
    const float* bias = (const float*)d_in[2];
    const float* CB   = (const float*)d_in[3];
    const float* GMB  = (const float*)d_in[4];
    float* out = (float*)d_out;

    zero_kernel<<<3, 256>>>();
    dim3 ggrid(10, 500);  // x: N tiles (640/64), y: M tiles (64000/128)
    gemm_kernel<<<ggrid, 256>>>(X, W, bias);
    epi_kernel<<<1000, 256>>>(GMB, CB, out);
    fin_kernel<<<1, 32>>>(out);
}

// round 7
// speedup vs baseline: 1.8213x; 1.8213x over previous
#include <cuda_runtime.h>
#include <cuda_fp16.h>
#include <cstdint>

// Problem constants
#define BT_    64000          // B*T
#define FIN_   1024
#define GV_    640            // GROUPS*NUM_VARS
#define NV_    320
#define VD_    128            // VAR_DIM
#define QELEMS (BT_ * 256)    // q output elements

#define TAU_RESCUE 0.02f

// ---------------------------------------------------------------------------
// Device scratch (no cudaMalloc allowed)
// ---------------------------------------------------------------------------
__device__ __align__(16) __half g_xh[(size_t)BT_ * FIN_];
__device__ __align__(16) __half g_xl[(size_t)BT_ * FIN_];
__device__ __align__(16) __half g_wh[(size_t)GV_ * FIN_];
__device__ __align__(16) __half g_wl[(size_t)GV_ * FIN_];
__device__ __align__(16) float  g_logits[(size_t)BT_ * GV_];
__device__ float        g_probsum[GV_];
__device__ unsigned int g_counts[GV_];

// ---------------------------------------------------------------------------
// PTX helpers (base-target only: cp.async / ldmatrix / mma.sync)
// ---------------------------------------------------------------------------
__device__ __forceinline__ uint32_t smem_u32(const void* p) {
    uint32_t a;
    asm("{ .reg .u64 t; cvta.to.shared.u64 t, %1; cvt.u32.u64 %0, t; }" : "=r"(a) : "l"(p));
    return a;
}
__device__ __forceinline__ void cpasync16(uint32_t dst, const void* src) {
    asm volatile("cp.async.cg.shared.global [%0], [%1], 16;" :: "r"(dst), "l"(src));
}
#define CP_COMMIT() asm volatile("cp.async.commit_group;")
#define CP_WAIT1()  asm volatile("cp.async.wait_group 1;")
#define CP_WAIT0()  asm volatile("cp.async.wait_group 0;")

#define LDM4(r, addr) \
    asm volatile("ldmatrix.sync.aligned.m8n8.x4.shared.b16 {%0,%1,%2,%3}, [%4];" \
                 : "=r"((r)[0]), "=r"((r)[1]), "=r"((r)[2]), "=r"((r)[3]) : "r"(addr))

#define MMA16816(d, a, b0r, b1r) \
    asm volatile("mma.sync.aligned.m16n8k16.row.col.f32.f16.f16.f32 " \
                 "{%0,%1,%2,%3},{%4,%5,%6,%7},{%8,%9},{%0,%1,%2,%3};" \
                 : "+f"((d)[0]), "+f"((d)[1]), "+f"((d)[2]), "+f"((d)[3]) \
                 : "r"((a)[0]), "r"((a)[1]), "r"((a)[2]), "r"((a)[3]), "r"(b0r), "r"(b1r))

// ---------------------------------------------------------------------------
// fp16x2 split kernels
// ---------------------------------------------------------------------------
__device__ __forceinline__ void split2(float x, __half& h, __half& l) {
    h = __float2half(x);
    l = __float2half(x - __half2float(h));
}

__global__ __launch_bounds__(256) void xsplit_kernel(const float* __restrict__ X) {
    const size_t base = ((size_t)blockIdx.x * 256 + threadIdx.x) * 8;
    const float4 v0 = *(const float4*)(X + base);
    const float4 v1 = *(const float4*)(X + base + 4);
    const float e[8] = {v0.x, v0.y, v0.z, v0.w, v1.x, v1.y, v1.z, v1.w};
    __half ph[8], pl[8];
#pragma unroll
    for (int i = 0; i < 8; i++) split2(e[i], ph[i], pl[i]);
    *(uint4*)(g_xh + base) = *(uint4*)ph;
    *(uint4*)(g_xl + base) = *(uint4*)pl;
}

__global__ __launch_bounds__(256) void wsplit_kernel(const float* __restrict__ W) {
    const size_t base = ((size_t)blockIdx.x * 256 + threadIdx.x) * 8;
    const float4 v0 = *(const float4*)(W + base);
    const float4 v1 = *(const float4*)(W + base + 4);
    const float e[8] = {v0.x, v0.y, v0.z, v0.w, v1.x, v1.y, v1.z, v1.w};
    __half ph[8], pl[8];
#pragma unroll
    for (int i = 0; i < 8; i++) split2(e[i], ph[i], pl[i]);
    *(uint4*)(g_wh + base) = *(uint4*)ph;
    *(uint4*)(g_wl + base) = *(uint4*)pl;
}

__global__ void zero_kernel() {
    int i = blockIdx.x * blockDim.x + threadIdx.x;
    if (i < GV_) { g_probsum[i] = 0.0f; g_counts[i] = 0u; }
}

// ---------------------------------------------------------------------------
// GEMM: logits = X @ W^T + bias, fp16x2 3-term via mma.sync m16n8k16
// CTA: 128(M) x 128(N), K-chunks of 64, double-buffered cp.async.
// 8 warps: warp_m = wid&1 (64 rows), warp_n = wid>>1 (32 cols).
// ---------------------------------------------------------------------------
#define PADH   72                       // halfs per smem row (144B; conflict-free)
#define TILEB  (128 * PADH * 2)         // 18432 bytes per tile
#define STAGEB (4 * TILEB)              // Ah, Al, Bh, Bl
#define GSMEM  (2 * STAGEB)             // 147456 bytes

__device__ __forceinline__ void load_stage(uint32_t sbase, int m0, int n0, int k0, int tid) {
#pragma unroll
    for (int i = 0; i < 4; i++) {
        const int e   = i * 256 + tid;      // 0..1023
        const int row = e >> 3;
        const int seg = e & 7;
        const uint32_t doff = (uint32_t)row * 144 + seg * 16;
        const size_t ka = (size_t)(m0 + row) * FIN_ + k0 + seg * 8;
        const size_t kb = (size_t)(n0 + row) * FIN_ + k0 + seg * 8;
        cpasync16(sbase + 0 * TILEB + doff, g_xh + ka);
        cpasync16(sbase + 1 * TILEB + doff, g_xl + ka);
        cpasync16(sbase + 2 * TILEB + doff, g_wh + kb);
        cpasync16(sbase + 3 * TILEB + doff, g_wl + kb);
    }
}

__global__ __launch_bounds__(256, 1) void gemm_kernel(const float* __restrict__ bias) {
    extern __shared__ char sm[];
    const uint32_t smb = smem_u32(sm);
    const int tid = threadIdx.x;
    const int wid = tid >> 5;
    const int lid = tid & 31;
    const int wm  = wid & 1;        // 0..1
    const int wn  = wid >> 1;       // 0..3
    const int n0  = blockIdx.x * 128;
    const int m0  = blockIdx.y * 128;

    float acc[4][4][4];
#pragma unroll
    for (int a = 0; a < 4; a++)
#pragma unroll
        for (int b = 0; b < 4; b++)
#pragma unroll
            for (int c = 0; c < 4; c++) acc[a][b][c] = 0.0f;

    // lane-constant ldmatrix offsets
    const int rowA  = (lid & 7) + ((lid >> 3) & 1) * 8;
    const int kselA = (lid >> 4) * 8;
    const int nB    = (lid >> 4) * 8 + (lid & 7);
    const int kselB = ((lid >> 3) & 1) * 8;
    const uint32_t aoff = (uint32_t)(wm * 64 + rowA) * 144 + kselA * 2;
    const uint32_t boff = (uint32_t)(wn * 32 + nB) * 144 + kselB * 2;

    load_stage(smb, m0, n0, 0, tid);
    CP_COMMIT();

    for (int c = 0; c < 16; c++) {
        const int nk = c + 1;
        if (nk < 16) {
            load_stage(smb + (nk & 1) * STAGEB, m0, n0, nk * 64, tid);
            CP_COMMIT();
            CP_WAIT1();          // current stage's group complete; next may fly
        } else {
            CP_WAIT0();          // last chunk: full drain
        }
        __syncthreads();

        const uint32_t sbase = smb + (c & 1) * STAGEB;
#pragma unroll
        for (int ks = 0; ks < 4; ks++) {
            uint32_t ah[4][4], al[4][4], bh[2][4], bl[2][4];
#pragma unroll
            for (int mt = 0; mt < 4; mt++) {
                const uint32_t ad = sbase + aoff + mt * (16 * 144) + ks * 32;
                LDM4(ah[mt], ad);
                LDM4(al[mt], ad + TILEB);
            }
#pragma unroll
            for (int nt2 = 0; nt2 < 2; nt2++) {
                const uint32_t bd = sbase + 2 * TILEB + boff + nt2 * (16 * 144) + ks * 32;
                LDM4(bh[nt2], bd);
                LDM4(bl[nt2], bd + TILEB);
            }
#pragma unroll
            for (int mt = 0; mt < 4; mt++)
#pragma unroll
                for (int nt = 0; nt < 4; nt++) {
                    const uint32_t bh0 = bh[nt >> 1][(nt & 1) * 2];
                    const uint32_t bh1 = bh[nt >> 1][(nt & 1) * 2 + 1];
                    const uint32_t bl0 = bl[nt >> 1][(nt & 1) * 2];
                    const uint32_t bl1 = bl[nt >> 1][(nt & 1) * 2 + 1];
                    MMA16816(acc[mt][nt], ah[mt], bh0, bh1);
                    MMA16816(acc[mt][nt], ah[mt], bl0, bl1);
                    MMA16816(acc[mt][nt], al[mt], bh0, bh1);
                }
        }
        __syncthreads();
    }

    // write logits (+bias)
    const int g   = lid >> 2;
    const int tig = lid & 3;
#pragma unroll
    for (int nt = 0; nt < 4; nt++) {
        const int col = n0 + wn * 32 + nt * 8 + tig * 2;
        const float b0 = __ldg(bias + col);
        const float b1 = __ldg(bias + col + 1);
#pragma unroll
        for (int mt = 0; mt < 4; mt++) {
            const int r0 = m0 + wm * 64 + mt * 16 + g;
            float2 v0 = make_float2(acc[mt][nt][0] + b0, acc[mt][nt][1] + b1);
            float2 v1 = make_float2(acc[mt][nt][2] + b0, acc[mt][nt][3] + b1);
            *(float2*)&g_logits[(size_t)r0 * GV_ + col]       = v0;
            *(float2*)&g_logits[(size_t)(r0 + 8) * GV_ + col] = v1;
        }
    }
}

// ---------------------------------------------------------------------------
// Epilogue: 1 warp per (row, group). Raw argmax -> counts; softmax -> probsum;
// gumbel top-2; near ties re-decided with ROUND-2 NUMERICS: sequential fp32
// fmaf dot in ascending k order (matches the fp32 SIMT kernel that passed).
// ---------------------------------------------------------------------------
__device__ __forceinline__ bool better(float v, int i, float v2, int i2) {
    return (v > v2) || (v == v2 && i < i2);
}

// Sequential fp32 dot, ascending k, single fmaf chain — replicates round-2 GEMM
__device__ __noinline__ float seq_dot(const float* __restrict__ xr,
                                      const float* __restrict__ wr) {
    float s = 0.0f;
#pragma unroll 8
    for (int k = 0; k < FIN_; k++) s = fmaf(__ldg(xr + k), __ldg(wr + k), s);
    return s;
}

__global__ __launch_bounds__(256) void epi_kernel(const float* __restrict__ X,
                                                  const float* __restrict__ W,
                                                  const float* __restrict__ bias,
                                                  const float* __restrict__ GMB,
                                                  const float* __restrict__ CB,
                                                  float* __restrict__ out) {
    __shared__ float        sprob[GV_];
    __shared__ unsigned int scnt[GV_];
    const int tid = threadIdx.x;
    for (int i = tid; i < GV_; i += 256) { sprob[i] = 0.0f; scnt[i] = 0u; }
    __syncthreads();

    const int warp = tid >> 5;
    const int lane = tid & 31;
    const int g    = warp & 1;
    const int slot = warp >> 1;
    const int rbase = blockIdx.x * 64 + slot;
    const int nbase = g * NV_;

    float pacc[10];
#pragma unroll
    for (int j = 0; j < 10; j++) pacc[j] = 0.0f;

    for (int it = 0; it < 16; it++) {
        const int row = rbase + it * 4;
        const float* lp = g_logits + (size_t)row * GV_ + nbase;

        float lv[10];
#pragma unroll
        for (int j = 0; j < 10; j++) lv[j] = lp[j * 32 + lane];

        // ---- raw argmax (approx ok: only moves one count in 64000) ----
        float bm = lv[0];
        int   bi = lane;
#pragma unroll
        for (int j = 1; j < 10; j++)
            if (lv[j] > bm) { bm = lv[j]; bi = j * 32 + lane; }
#pragma unroll
        for (int off = 16; off > 0; off >>= 1) {
            const float om = __shfl_xor_sync(0xffffffffu, bm, off);
            const int   oi = __shfl_xor_sync(0xffffffffu, bi, off);
            if (om > bm || (om == bm && oi < bi)) { bm = om; bi = oi; }
        }
        if (lane == 0) atomicAdd(&scnt[nbase + bi], 1u);

        // ---- softmax accumulate ----
        float ev[10];
        float s = 0.0f;
#pragma unroll
        for (int j = 0; j < 10; j++) { ev[j] = __expf(lv[j] - bm); s += ev[j]; }
#pragma unroll
        for (int off = 16; off > 0; off >>= 1) s += __shfl_xor_sync(0xffffffffu, s, off);
        const float inv = 1.0f / s;
#pragma unroll
        for (int j = 0; j < 10; j++) pacc[j] += ev[j] * inv;

        // ---- gumbel top-2 ----
        const float* gp = GMB + (size_t)row * GV_ + nbase;
        float m1 = -1e30f, m2 = -1e30f;
        int   i1 = 0x7fffffff, i2 = 0x7fffffff;
#pragma unroll
        for (int j = 0; j < 10; j++) {
            const float t = lv[j] + gp[j * 32 + lane];
            const int idx = j * 32 + lane;
            if (t > m1) { m2 = m1; i2 = i1; m1 = t; i1 = idx; }
            else if (t > m2) { m2 = t; i2 = idx; }
        }
#pragma unroll
        for (int off = 16; off > 0; off >>= 1) {
            const float om1 = __shfl_xor_sync(0xffffffffu, m1, off);
            const int   oi1 = __shfl_xor_sync(0xffffffffu, i1, off);
            const float om2 = __shfl_xor_sync(0xffffffffu, m2, off);
            const int   oi2 = __shfl_xor_sync(0xffffffffu, i2, off);
            if (better(om1, oi1, m1, i1)) {
                if (better(m1, i1, om2, oi2)) { m2 = m1; i2 = i1; }
                else                          { m2 = om2; i2 = oi2; }
                m1 = om1; i1 = oi1;
            } else if (better(om1, oi1, m2, i2)) {
                m2 = om1; i2 = oi1;
            }
        }

        int winner = i1;
        if (m1 - m2 < TAU_RESCUE) {
            // Re-decide with round-2 numerics: sequential fp32 fmaf in k order,
            // + bias (fp32 add), + gumbel (fp32 add), strict > / min-index.
            int w_local = 0;
            if (lane == 0) {
                const float* xr = X + (size_t)row * FIN_;
                const float e1 = seq_dot(xr, W + (size_t)(nbase + i1) * FIN_)
                                 + __ldg(bias + nbase + i1) + __ldg(gp + i1);
                const float e2 = seq_dot(xr, W + (size_t)(nbase + i2) * FIN_)
                                 + __ldg(bias + nbase + i2) + __ldg(gp + i2);
                w_local = better(e1, i1, e2, i2) ? i1 : i2;
            }
            winner = __shfl_sync(0xffffffffu, w_local, 0);
        }

        // q gather: 32 lanes x 16B = full 512B codebook row
        const float4* src = (const float4*)(CB + (size_t)(nbase + winner) * VD_);
        float4*       dst = (float4*)(out + ((size_t)row * 2 + g) * VD_);
        dst[lane] = src[lane];
    }

    // merge per-warp prob accumulators (4 warps/group collide) -> global
#pragma unroll
    for (int j = 0; j < 10; j++) atomicAdd(&sprob[nbase + j * 32 + lane], pacc[j]);
    __syncthreads();
    for (int i = tid; i < GV_; i += 256) {
        atomicAdd(&g_probsum[i], sprob[i]);
        atomicAdd(&g_counts[i], scnt[i]);
    }
}

// ---------------------------------------------------------------------------
// Perplexity scalars. out layout: [q | code_ppl | prob_ppl]
// ---------------------------------------------------------------------------
__global__ void fin_kernel(float* __restrict__ out) {
    const int lane = threadIdx.x;
    const float invBT = 1.0f / (float)BT_;
    float Hs[2], Hc[2];
#pragma unroll
    for (int g = 0; g < 2; g++) {
        float hs = 0.0f, hc = 0.0f;
        for (int j = 0; j < 10; j++) {
            const int v = g * NV_ + j * 32 + lane;
            const float p = g_probsum[v] * invBT;
            const float c = (float)g_counts[v] * invBT;
            hs += p * logf(p + 1e-7f);
            hc += c * logf(c + 1e-7f);
        }
#pragma unroll
        for (int off = 16; off > 0; off >>= 1) {
            hs += __shfl_xor_sync(0xffffffffu, hs, off);
            hc += __shfl_xor_sync(0xffffffffu, hc, off);
        }
        Hs[g] = hs; Hc[g] = hc;
    }
    if (lane == 0) {
        out[QELEMS]     = expf(-Hc[0]) + expf(-Hc[1]);
        out[QELEMS + 1] = expf(-Hs[0]) + expf(-Hs[1]);
    }
}

// ---------------------------------------------------------------------------
// Launch
// inputs: 0=x, 1=proj_w, 2=proj_b, 3=codebook, 4=gumbel ; output f32
// ---------------------------------------------------------------------------
extern "C" void kernel_launch(void* const* d_in, const int* in_sizes, int n_in,
                              void* d_out, int out_size) {
    (void)in_sizes; (void)n_in; (void)out_size;
    const float* X    = (const float*)d_in[0];
    const float* W    = (const float*)d_in[1];
    const float* bias = (const float*)d_in[2];
    const float* CB   = (const float*)d_in[3];
    const float* GMB  = (const float*)d_in[4];
    float* out = (float*)d_out;

    cudaFuncSetAttribute(gemm_kernel, cudaFuncAttributeMaxDynamicSharedMemorySize, GSMEM);

    zero_kernel<<<3, 256>>>();
    xsplit_kernel<<<32000, 256>>>(X);
    wsplit_kernel<<<320, 256>>>(W);
    dim3 ggrid(5, 500);   // x: N tiles (640/128), y: M tiles (64000/128)
    gemm_kernel<<<ggrid, 256, GSMEM>>>(bias);
    epi_kernel<<<1000, 256>>>(X, W, bias, GMB, CB, out);
    fin_kernel<<<1, 32>>>(out);
}

// round 8
// speedup vs baseline: 1.8314x; 1.0055x over previous
#include <cuda_runtime.h>
#include <cuda_fp16.h>
#include <cstdint>

// Problem constants
#define BT_    64000          // B*T
#define FIN_   1024
#define GV_    640            // GROUPS*NUM_VARS
#define NV_    320
#define VD_    128            // VAR_DIM
#define QELEMS (BT_ * 256)    // q output elements

#define TAU_RESCUE 0.02f

// ---------------------------------------------------------------------------
// Device scratch (no cudaMalloc allowed)
// ---------------------------------------------------------------------------
__device__ __align__(16) __half g_xh[(size_t)BT_ * FIN_];
__device__ __align__(16) __half g_xl[(size_t)BT_ * FIN_];
__device__ __align__(16) __half g_wh[(size_t)GV_ * FIN_];
__device__ __align__(16) __half g_wl[(size_t)GV_ * FIN_];
__device__ __align__(16) float  g_logits[(size_t)BT_ * GV_];
__device__ float        g_probsum[GV_];
__device__ unsigned int g_counts[GV_];

// ---------------------------------------------------------------------------
// PTX helpers (base-target only: cp.async / ldmatrix / mma.sync)
// ---------------------------------------------------------------------------
__device__ __forceinline__ uint32_t smem_u32(const void* p) {
    uint32_t a;
    asm("{ .reg .u64 t; cvta.to.shared.u64 t, %1; cvt.u32.u64 %0, t; }" : "=r"(a) : "l"(p));
    return a;
}
__device__ __forceinline__ void cpasync16(uint32_t dst, const void* src) {
    asm volatile("cp.async.cg.shared.global [%0], [%1], 16;" :: "r"(dst), "l"(src));
}
#define CP_COMMIT() asm volatile("cp.async.commit_group;")
#define CP_WAIT1()  asm volatile("cp.async.wait_group 1;")
#define CP_WAIT0()  asm volatile("cp.async.wait_group 0;")

#define LDM4(r, addr) \
    asm volatile("ldmatrix.sync.aligned.m8n8.x4.shared.b16 {%0,%1,%2,%3}, [%4];" \
                 : "=r"((r)[0]), "=r"((r)[1]), "=r"((r)[2]), "=r"((r)[3]) : "r"(addr))

#define MMA16816(d, a, b0r, b1r) \
    asm volatile("mma.sync.aligned.m16n8k16.row.col.f32.f16.f16.f32 " \
                 "{%0,%1,%2,%3},{%4,%5,%6,%7},{%8,%9},{%0,%1,%2,%3};" \
                 : "+f"((d)[0]), "+f"((d)[1]), "+f"((d)[2]), "+f"((d)[3]) \
                 : "r"((a)[0]), "r"((a)[1]), "r"((a)[2]), "r"((a)[3]), "r"(b0r), "r"(b1r))

// ---------------------------------------------------------------------------
// fp16x2 split kernels
// ---------------------------------------------------------------------------
__device__ __forceinline__ void split2(float x, __half& h, __half& l) {
    h = __float2half(x);
    l = __float2half(x - __half2float(h));
}

__global__ __launch_bounds__(256) void xsplit_kernel(const float* __restrict__ X) {
    const size_t base = ((size_t)blockIdx.x * 256 + threadIdx.x) * 8;
    const float4 v0 = *(const float4*)(X + base);
    const float4 v1 = *(const float4*)(X + base + 4);
    const float e[8] = {v0.x, v0.y, v0.z, v0.w, v1.x, v1.y, v1.z, v1.w};
    __half ph[8], pl[8];
#pragma unroll
    for (int i = 0; i < 8; i++) split2(e[i], ph[i], pl[i]);
    *(uint4*)(g_xh + base) = *(uint4*)ph;
    *(uint4*)(g_xl + base) = *(uint4*)pl;
}

__global__ __launch_bounds__(256) void wsplit_kernel(const float* __restrict__ W) {
    const size_t base = ((size_t)blockIdx.x * 256 + threadIdx.x) * 8;
    const float4 v0 = *(const float4*)(W + base);
    const float4 v1 = *(const float4*)(W + base + 4);
    const float e[8] = {v0.x, v0.y, v0.z, v0.w, v1.x, v1.y, v1.z, v1.w};
    __half ph[8], pl[8];
#pragma unroll
    for (int i = 0; i < 8; i++) split2(e[i], ph[i], pl[i]);
    *(uint4*)(g_wh + base) = *(uint4*)ph;
    *(uint4*)(g_wl + base) = *(uint4*)pl;
}

__global__ void zero_kernel() {
    int i = blockIdx.x * blockDim.x + threadIdx.x;
    if (i < GV_) { g_probsum[i] = 0.0f; g_counts[i] = 0u; }
}

// ---------------------------------------------------------------------------
// GEMM: logits = X @ W^T + bias, fp16x2 3-term via mma.sync m16n8k16
// CTA: 128(M) x 128(N), K-chunks of 32, double-buffered cp.async.
// Stage = 40KB -> 80KB/CTA -> 2 CTAs/SM (cross-CTA latency hiding).
// 8 warps: warp_m = wid&1 (64 rows), warp_n = wid>>1 (32 cols).
// ---------------------------------------------------------------------------
#define PADH   40                       // halfs per smem row (80B; conflict-free:
                                        // 80B stride mod 128 covers all 16B offsets)
#define ROWB   80                       // bytes per row
#define TILEB  (128 * ROWB)             // 10240 bytes per tile
#define STAGEB (4 * TILEB)              // Ah, Al, Bh, Bl = 40960
#define GSMEM  (2 * STAGEB)             // 81920 bytes

#define NCHUNK 32                       // 1024 / 32

__device__ __forceinline__ void load_stage(uint32_t sbase, int m0, int n0, int k0, int tid) {
#pragma unroll
    for (int i = 0; i < 2; i++) {
        const int e   = i * 256 + tid;      // 0..511
        const int row = e >> 2;             // 0..127
        const int seg = e & 3;              // 4 segs of 8 halfs = 32 k
        const uint32_t doff = (uint32_t)row * ROWB + seg * 16;
        const size_t ka = (size_t)(m0 + row) * FIN_ + k0 + seg * 8;
        const size_t kb = (size_t)(n0 + row) * FIN_ + k0 + seg * 8;
        cpasync16(sbase + 0 * TILEB + doff, g_xh + ka);
        cpasync16(sbase + 1 * TILEB + doff, g_xl + ka);
        cpasync16(sbase + 2 * TILEB + doff, g_wh + kb);
        cpasync16(sbase + 3 * TILEB + doff, g_wl + kb);
    }
}

__global__ __launch_bounds__(256, 2) void gemm_kernel(const float* __restrict__ bias) {
    extern __shared__ char sm[];
    const uint32_t smb = smem_u32(sm);
    const int tid = threadIdx.x;
    const int wid = tid >> 5;
    const int lid = tid & 31;
    const int wm  = wid & 1;        // 0..1
    const int wn  = wid >> 1;       // 0..3
    const int n0  = blockIdx.x * 128;
    const int m0  = blockIdx.y * 128;

    float acc[4][4][4];
#pragma unroll
    for (int a = 0; a < 4; a++)
#pragma unroll
        for (int b = 0; b < 4; b++)
#pragma unroll
            for (int c = 0; c < 4; c++) acc[a][b][c] = 0.0f;

    // lane-constant ldmatrix offsets (same operand mapping as R7, row stride 80B)
    const int rowA  = (lid & 7) + ((lid >> 3) & 1) * 8;
    const int kselA = (lid >> 4) * 8;
    const int nB    = (lid >> 4) * 8 + (lid & 7);
    const int kselB = ((lid >> 3) & 1) * 8;
    const uint32_t aoff = (uint32_t)(wm * 64 + rowA) * ROWB + kselA * 2;
    const uint32_t boff = (uint32_t)(wn * 32 + nB) * ROWB + kselB * 2;

    load_stage(smb, m0, n0, 0, tid);
    CP_COMMIT();

    for (int c = 0; c < NCHUNK; c++) {
        const int nk = c + 1;
        if (nk < NCHUNK) {
            load_stage(smb + (nk & 1) * STAGEB, m0, n0, nk * 32, tid);
            CP_COMMIT();
            CP_WAIT1();          // current stage's group complete; next may fly
        } else {
            CP_WAIT0();          // last chunk: full drain
        }
        __syncthreads();

        const uint32_t sbase = smb + (c & 1) * STAGEB;
#pragma unroll
        for (int ks = 0; ks < 2; ks++) {
            uint32_t bh[2][4], bl[2][4];
#pragma unroll
            for (int nt2 = 0; nt2 < 2; nt2++) {
                const uint32_t bd = sbase + 2 * TILEB + boff + nt2 * (16 * ROWB) + ks * 32;
                LDM4(bh[nt2], bd);
                LDM4(bl[nt2], bd + TILEB);
            }
#pragma unroll
            for (int mt = 0; mt < 4; mt++) {
                uint32_t ah[4], al[4];
                const uint32_t ad = sbase + aoff + mt * (16 * ROWB) + ks * 32;
                LDM4(ah, ad);
                LDM4(al, ad + TILEB);
#pragma unroll
                for (int nt = 0; nt < 4; nt++) {
                    const uint32_t bh0 = bh[nt >> 1][(nt & 1) * 2];
                    const uint32_t bh1 = bh[nt >> 1][(nt & 1) * 2 + 1];
                    const uint32_t bl0 = bl[nt >> 1][(nt & 1) * 2];
                    const uint32_t bl1 = bl[nt >> 1][(nt & 1) * 2 + 1];
                    MMA16816(acc[mt][nt], ah, bh0, bh1);
                    MMA16816(acc[mt][nt], ah, bl0, bl1);
                    MMA16816(acc[mt][nt], al, bh0, bh1);
                }
            }
        }
        __syncthreads();
    }

    // write logits (+bias)
    const int g   = lid >> 2;
    const int tig = lid & 3;
#pragma unroll
    for (int nt = 0; nt < 4; nt++) {
        const int col = n0 + wn * 32 + nt * 8 + tig * 2;
        const float b0 = __ldg(bias + col);
        const float b1 = __ldg(bias + col + 1);
#pragma unroll
        for (int mt = 0; mt < 4; mt++) {
            const int r0 = m0 + wm * 64 + mt * 16 + g;
            float2 v0 = make_float2(acc[mt][nt][0] + b0, acc[mt][nt][1] + b1);
            float2 v1 = make_float2(acc[mt][nt][2] + b0, acc[mt][nt][3] + b1);
            *(float2*)&g_logits[(size_t)r0 * GV_ + col]       = v0;
            *(float2*)&g_logits[(size_t)(r0 + 8) * GV_ + col] = v1;
        }
    }
}

// ---------------------------------------------------------------------------
// Epilogue: 1 warp per (row, group). Raw argmax -> counts; softmax -> probsum;
// gumbel top-2; near ties re-decided with ROUND-2 NUMERICS: sequential fp32
// fmaf dot in ascending k order (matches the fp32 SIMT kernel that passed).
// ---------------------------------------------------------------------------
__device__ __forceinline__ bool better(float v, int i, float v2, int i2) {
    return (v > v2) || (v == v2 && i < i2);
}

// Sequential fp32 dot, ascending k, single fmaf chain — replicates round-2 GEMM
__device__ __noinline__ float seq_dot(const float* __restrict__ xr,
                                      const float* __restrict__ wr) {
    float s = 0.0f;
#pragma unroll 8
    for (int k = 0; k < FIN_; k++) s = fmaf(__ldg(xr + k), __ldg(wr + k), s);
    return s;
}

__global__ __launch_bounds__(256) void epi_kernel(const float* __restrict__ X,
                                                  const float* __restrict__ W,
                                                  const float* __restrict__ bias,
                                                  const float* __restrict__ GMB,
                                                  const float* __restrict__ CB,
                                                  float* __restrict__ out) {
    __shared__ float        sprob[GV_];
    __shared__ unsigned int scnt[GV_];
    const int tid = threadIdx.x;
    for (int i = tid; i < GV_; i += 256) { sprob[i] = 0.0f; scnt[i] = 0u; }
    __syncthreads();

    const int warp = tid >> 5;
    const int lane = tid & 31;
    const int g    = warp & 1;
    const int slot = warp >> 1;
    const int rbase = blockIdx.x * 64 + slot;
    const int nbase = g * NV_;

    float pacc[10];
#pragma unroll
    for (int j = 0; j < 10; j++) pacc[j] = 0.0f;

    for (int it = 0; it < 16; it++) {
        const int row = rbase + it * 4;
        const float* lp = g_logits + (size_t)row * GV_ + nbase;

        float lv[10];
#pragma unroll
        for (int j = 0; j < 10; j++) lv[j] = lp[j * 32 + lane];

        // ---- raw argmax (approx ok: only moves one count in 64000) ----
        float bm = lv[0];
        int   bi = lane;
#pragma unroll
        for (int j = 1; j < 10; j++)
            if (lv[j] > bm) { bm = lv[j]; bi = j * 32 + lane; }
#pragma unroll
        for (int off = 16; off > 0; off >>= 1) {
            const float om = __shfl_xor_sync(0xffffffffu, bm, off);
            const int   oi = __shfl_xor_sync(0xffffffffu, bi, off);
            if (om > bm || (om == bm && oi < bi)) { bm = om; bi = oi; }
        }
        if (lane == 0) atomicAdd(&scnt[nbase + bi], 1u);

        // ---- softmax accumulate ----
        float ev[10];
        float s = 0.0f;
#pragma unroll
        for (int j = 0; j < 10; j++) { ev[j] = __expf(lv[j] - bm); s += ev[j]; }
#pragma unroll
        for (int off = 16; off > 0; off >>= 1) s += __shfl_xor_sync(0xffffffffu, s, off);
        const float inv = 1.0f / s;
#pragma unroll
        for (int j = 0; j < 10; j++) pacc[j] += ev[j] * inv;

        // ---- gumbel top-2 ----
        const float* gp = GMB + (size_t)row * GV_ + nbase;
        float m1 = -1e30f, m2 = -1e30f;
        int   i1 = 0x7fffffff, i2 = 0x7fffffff;
#pragma unroll
        for (int j = 0; j < 10; j++) {
            const float t = lv[j] + gp[j * 32 + lane];
            const int idx = j * 32 + lane;
            if (t > m1) { m2 = m1; i2 = i1; m1 = t; i1 = idx; }
            else if (t > m2) { m2 = t; i2 = idx; }
        }
#pragma unroll
        for (int off = 16; off > 0; off >>= 1) {
            const float om1 = __shfl_xor_sync(0xffffffffu, m1, off);
            const int   oi1 = __shfl_xor_sync(0xffffffffu, i1, off);
            const float om2 = __shfl_xor_sync(0xffffffffu, m2, off);
            const int   oi2 = __shfl_xor_sync(0xffffffffu, i2, off);
            if (better(om1, oi1, m1, i1)) {
                if (better(m1, i1, om2, oi2)) { m2 = m1; i2 = i1; }
                else                          { m2 = om2; i2 = oi2; }
                m1 = om1; i1 = oi1;
            } else if (better(om1, oi1, m2, i2)) {
                m2 = om1; i2 = oi1;
            }
        }

        int winner = i1;
        if (m1 - m2 < TAU_RESCUE) {
            // Re-decide with round-2 numerics: sequential fp32 fmaf in k order,
            // + bias (fp32 add), + gumbel (fp32 add), strict > / min-index.
            int w_local = 0;
            if (lane == 0) {
                const float* xr = X + (size_t)row * FIN_;
                const float e1 = seq_dot(xr, W + (size_t)(nbase + i1) * FIN_)
                                 + __ldg(bias + nbase + i1) + __ldg(gp + i1);
                const float e2 = seq_dot(xr, W + (size_t)(nbase + i2) * FIN_)
                                 + __ldg(bias + nbase + i2) + __ldg(gp + i2);
                w_local = better(e1, i1, e2, i2) ? i1 : i2;
            }
            winner = __shfl_sync(0xffffffffu, w_local, 0);
        }

        // q gather: 32 lanes x 16B = full 512B codebook row
        const float4* src = (const float4*)(CB + (size_t)(nbase + winner) * VD_);
        float4*       dst = (float4*)(out + ((size_t)row * 2 + g) * VD_);
        dst[lane] = src[lane];
    }

    // merge per-warp prob accumulators (4 warps/group collide) -> global
#pragma unroll
    for (int j = 0; j < 10; j++) atomicAdd(&sprob[nbase + j * 32 + lane], pacc[j]);
    __syncthreads();
    for (int i = tid; i < GV_; i += 256) {
        atomicAdd(&g_probsum[i], sprob[i]);
        atomicAdd(&g_counts[i], scnt[i]);
    }
}

// ---------------------------------------------------------------------------
// Perplexity scalars. out layout: [q | code_ppl | prob_ppl]
// ---------------------------------------------------------------------------
__global__ void fin_kernel(float* __restrict__ out) {
    const int lane = threadIdx.x;
    const float invBT = 1.0f / (float)BT_;
    float Hs[2], Hc[2];
#pragma unroll
    for (int g = 0; g < 2; g++) {
        float hs = 0.0f, hc = 0.0f;
        for (int j = 0; j < 10; j++) {
            const int v = g * NV_ + j * 32 + lane;
            const float p = g_probsum[v] * invBT;
            const float c = (float)g_counts[v] * invBT;
            hs += p * logf(p + 1e-7f);
            hc += c * logf(c + 1e-7f);
        }
#pragma unroll
        for (int off = 16; off > 0; off >>= 1) {
            hs += __shfl_xor_sync(0xffffffffu, hs, off);
            hc += __shfl_xor_sync(0xffffffffu, hc, off);
        }
        Hs[g] = hs; Hc[g] = hc;
    }
    if (lane == 0) {
        out[QELEMS]     = expf(-Hc[0]) + expf(-Hc[1]);
        out[QELEMS + 1] = expf(-Hs[0]) + expf(-Hs[1]);
    }
}

// ---------------------------------------------------------------------------
// Launch
// inputs: 0=x, 1=proj_w, 2=proj_b, 3=codebook, 4=gumbel ; output f32
// ---------------------------------------------------------------------------
extern "C" void kernel_launch(void* const* d_in, const int* in_sizes, int n_in,
                              void* d_out, int out_size) {
    (void)in_sizes; (void)n_in; (void)out_size;
    const float* X    = (const float*)d_in[0];
    const float* W    = (const float*)d_in[1];
    const float* bias = (const float*)d_in[2];
    const float* CB   = (const float*)d_in[3];
    const float* GMB  = (const float*)d_in[4];
    float* out = (float*)d_out;

    cudaFuncSetAttribute(gemm_kernel, cudaFuncAttributeMaxDynamicSharedMemorySize, GSMEM);

    zero_kernel<<<3, 256>>>();
    xsplit_kernel<<<32000, 256>>>(X);
    wsplit_kernel<<<320, 256>>>(W);
    dim3 ggrid(5, 500);   // x: N tiles (640/128), y: M tiles (64000/128)
    gemm_kernel<<<ggrid, 256, GSMEM>>>(bias);
    epi_kernel<<<1000, 256>>>(X, W, bias, GMB, CB, out);
    fin_kernel<<<1, 32>>>(out);
}